// round 1
// baseline (speedup 1.0000x reference)
#include <cuda_runtime.h>

// Problem constants
#define BATCH 32
#define NTOK  1024
#define FDIM  512
#define GRP   16
#define SEQ   64
#define DDIM  256
#define WIN   32
#define OCH   512
#define TOUT  993          // NTOK - WIN + 1
#define NEG_SLOPE 0.2f

// Scratch for the intermediate (B, N, D) = (32, 1024, 256) fp32 = 32 MB
__device__ float g_mid[BATCH * NTOK * DDIM];

#define BM 128
#define BN 128
#define BK 8

// ---------------------------------------------------------------------------
// Kernel 1: gather + grouped GEMM
//   mid[b, g*64+s, d] = sum_f x[b, idx[g,s], f] * W[g, f, d] + bias[g, d]
// grid: (N/BN=2, M/BM=16, G=16), block: 256
// M dimension = b*64 + s (2048 rows per group)
// ---------------------------------------------------------------------------
__global__ __launch_bounds__(256)
void gemm1_kernel(const float* __restrict__ x, const int* __restrict__ idx,
                  const float* __restrict__ W, const float* __restrict__ bias) {
    const int g  = blockIdx.z;
    const int m0 = blockIdx.y * BM;
    const int n0 = blockIdx.x * BN;
    const int tid = threadIdx.x;

    __shared__ float As[BK][BM];
    __shared__ float Bs[BK][BN];
    __shared__ int   rowbase[BM];   // (b*NTOK + token) per tile row

    if (tid < BM) {
        int m  = m0 + tid;
        int bb = m >> 6;            // m / 64
        int s  = m & 63;
        rowbase[tid] = bb * NTOK + idx[g * SEQ + s];
    }
    __syncthreads();

    const int a_row = tid >> 1;          // 0..127
    const int a_col = (tid & 1) * 4;     // 0 or 4
    const int b_row = tid >> 5;          // 0..7
    const int b_col = (tid & 31) * 4;    // 0..124

    const float* Wg = W + (long)g * FDIM * DDIM;
    const long a_base = (long)rowbase[a_row] * FDIM;

    float acc[8][8];
#pragma unroll
    for (int i = 0; i < 8; i++)
#pragma unroll
        for (int j = 0; j < 8; j++) acc[i][j] = 0.f;

    const int ty = tid >> 4;   // 0..15
    const int tx = tid & 15;   // 0..15

    for (int k0 = 0; k0 < FDIM; k0 += BK) {
        float4 av = *(const float4*)(x + a_base + k0 + a_col);
        As[a_col + 0][a_row] = av.x;
        As[a_col + 1][a_row] = av.y;
        As[a_col + 2][a_row] = av.z;
        As[a_col + 3][a_row] = av.w;
        *(float4*)&Bs[b_row][b_col] =
            *(const float4*)(Wg + (long)(k0 + b_row) * DDIM + n0 + b_col);
        __syncthreads();

#pragma unroll
        for (int kk = 0; kk < BK; kk++) {
            float4 a0 = *(const float4*)&As[kk][ty * 4];
            float4 a1 = *(const float4*)&As[kk][64 + ty * 4];
            float4 c0 = *(const float4*)&Bs[kk][tx * 4];
            float4 c1 = *(const float4*)&Bs[kk][64 + tx * 4];
            float rm[8] = {a0.x, a0.y, a0.z, a0.w, a1.x, a1.y, a1.z, a1.w};
            float rn[8] = {c0.x, c0.y, c0.z, c0.w, c1.x, c1.y, c1.z, c1.w};
#pragma unroll
            for (int i = 0; i < 8; i++)
#pragma unroll
                for (int j = 0; j < 8; j++)
                    acc[i][j] += rm[i] * rn[j];
        }
        __syncthreads();
    }

    // epilogue: write mid[b, g*64+s, d] (+ bias)
#pragma unroll
    for (int i = 0; i < 8; i++) {
        int mi = (i < 4) ? (ty * 4 + i) : (64 + ty * 4 + (i - 4));
        int m  = m0 + mi;
        int bb = m >> 6;
        int s  = m & 63;
        float* outrow = g_mid + ((long)(bb * NTOK + g * SEQ + s)) * DDIM + n0;
#pragma unroll
        for (int j = 0; j < 8; j++) {
            int nj = (j < 4) ? (tx * 4 + j) : (64 + tx * 4 + (j - 4));
            outrow[nj] = acc[i][j] + bias[g * DDIM + n0 + nj];
        }
    }
}

// ---------------------------------------------------------------------------
// Kernel 2: conv1d (window 32) as implicit GEMM + leaky ReLU
//   y[b, t, o] = leaky( sum_{k<8192} mid[b, t + k/256, k%256] * cw[k, o] + cb[o] )
//   K = 8192, M = 993 (per batch), N = 512
// grid: (OCH/BN=4, ceil(993/128)=8, B=32), block: 256
// ---------------------------------------------------------------------------
__global__ __launch_bounds__(256)
void conv_gemm_kernel(const float* __restrict__ cw, const float* __restrict__ cb,
                      float* __restrict__ y) {
    const int b  = blockIdx.z;
    const int t0 = blockIdx.y * BM;
    const int n0 = blockIdx.x * BN;
    const int tid = threadIdx.x;

    __shared__ float As[BK][BM];
    __shared__ float Bs[BK][BN];

    const int a_row = tid >> 1;          // 0..127 (t within tile)
    const int a_col = (tid & 1) * 4;     // 0 or 4 (k within chunk)
    const int b_row = tid >> 5;          // 0..7
    const int b_col = (tid & 31) * 4;

    const float* midb = g_mid + (long)b * NTOK * DDIM;

    float acc[8][8];
#pragma unroll
    for (int i = 0; i < 8; i++)
#pragma unroll
        for (int j = 0; j < 8; j++) acc[i][j] = 0.f;

    const int ty = tid >> 4;
    const int tx = tid & 15;

    const int KTOT = WIN * DDIM;   // 8192
    for (int k0 = 0; k0 < KTOT; k0 += BK) {
        // A tile: implicit im2col. k-chunk of 8 stays inside one w (256 % 8 == 0).
        int k = k0 + a_col;
        int w = k >> 8;            // k / 256
        int d = k & 255;
        int t = t0 + a_row + w;    // row in mid for this batch
        float4 av;
        if (t < NTOK) av = *(const float4*)(midb + (long)t * DDIM + d);
        else          av = make_float4(0.f, 0.f, 0.f, 0.f);
        As[a_col + 0][a_row] = av.x;
        As[a_col + 1][a_row] = av.y;
        As[a_col + 2][a_row] = av.z;
        As[a_col + 3][a_row] = av.w;

        // B tile: conv_w flattened is already [K=8192][O=512] row-major
        *(float4*)&Bs[b_row][b_col] =
            *(const float4*)(cw + (long)(k0 + b_row) * OCH + n0 + b_col);
        __syncthreads();

#pragma unroll
        for (int kk = 0; kk < BK; kk++) {
            float4 a0 = *(const float4*)&As[kk][ty * 4];
            float4 a1 = *(const float4*)&As[kk][64 + ty * 4];
            float4 c0 = *(const float4*)&Bs[kk][tx * 4];
            float4 c1 = *(const float4*)&Bs[kk][64 + tx * 4];
            float rm[8] = {a0.x, a0.y, a0.z, a0.w, a1.x, a1.y, a1.z, a1.w};
            float rn[8] = {c0.x, c0.y, c0.z, c0.w, c1.x, c1.y, c1.z, c1.w};
#pragma unroll
            for (int i = 0; i < 8; i++)
#pragma unroll
                for (int j = 0; j < 8; j++)
                    acc[i][j] += rm[i] * rn[j];
        }
        __syncthreads();
    }

    // epilogue: bias + leaky relu, guarded store (t < 993)
#pragma unroll
    for (int i = 0; i < 8; i++) {
        int mi = (i < 4) ? (ty * 4 + i) : (64 + ty * 4 + (i - 4));
        int t  = t0 + mi;
        if (t >= TOUT) continue;
        float* outrow = y + ((long)b * TOUT + t) * OCH + n0;
#pragma unroll
        for (int j = 0; j < 8; j++) {
            int nj = (j < 4) ? (tx * 4 + j) : (64 + tx * 4 + (j - 4));
            float v = acc[i][j] + cb[n0 + nj];
            outrow[nj] = (v >= 0.f) ? v : NEG_SLOPE * v;
        }
    }
}

// ---------------------------------------------------------------------------
extern "C" void kernel_launch(void* const* d_in, const int* in_sizes, int n_in,
                              void* d_out, int out_size) {
    const float* x    = (const float*)d_in[0];
    const int*   idx  = (const int*)  d_in[1];
    const float* W    = (const float*)d_in[2];
    const float* bias = (const float*)d_in[3];
    const float* cw   = (const float*)d_in[4];
    const float* cb   = (const float*)d_in[5];
    float* y = (float*)d_out;

    dim3 grid1(DDIM / BN, (BATCH * SEQ) / BM, GRP);   // (2, 16, 16)
    gemm1_kernel<<<grid1, 256>>>(x, idx, W, bias);

    dim3 grid2(OCH / BN, (TOUT + BM - 1) / BM, BATCH); // (4, 8, 32)
    conv_gemm_kernel<<<grid2, 256>>>(cw, cb, y);
}

// round 2
// speedup vs baseline: 3.0793x; 3.0793x over previous
#include <cuda_runtime.h>

// Problem constants
#define BATCH 32
#define NTOK  1024
#define FDIM  512
#define GRP   16
#define SEQ   64
#define DDIM  256
#define WIN   32
#define OCH   512
#define TOUT  993          // NTOK - WIN + 1
#define NEG_SLOPE 0.2f

// Scratch: intermediate (B, N, D) fp32 (tf32-rounded values), 32 MB
__device__ float g_mid[BATCH * NTOK * DDIM];
// Scratch: conv weights tf32-rounded, 16 MB  [K=8192][O=512]
__device__ float g_cw[WIN * DDIM * OCH];

__device__ __forceinline__ unsigned f2tf(float v) {
    unsigned r;
    asm("cvt.rna.tf32.f32 %0, %1;" : "=r"(r) : "f"(v));
    return r;
}

// ---------------------------------------------------------------------------
// Kernel 0: round conv_w to tf32 once
// ---------------------------------------------------------------------------
__global__ __launch_bounds__(256)
void cvt_cw_kernel(const float* __restrict__ cw) {
    int i = (blockIdx.x * 256 + threadIdx.x) * 4;
    float4 v = *(const float4*)(cw + i);
    unsigned* o = (unsigned*)(g_cw + i);
    o[0] = f2tf(v.x); o[1] = f2tf(v.y); o[2] = f2tf(v.z); o[3] = f2tf(v.w);
}

// ---------------------------------------------------------------------------
// Kernel 1: gather + grouped GEMM (FFMA fp32), output rounded to tf32
//   mid[b, g*64+s, d] = sum_f x[b, idx[g,s], f] * W[g, f, d] + bias[g, d]
// ---------------------------------------------------------------------------
#define BM1 128
#define BN1 128
#define BK1 8

__global__ __launch_bounds__(256)
void gemm1_kernel(const float* __restrict__ x, const int* __restrict__ idx,
                  const float* __restrict__ W, const float* __restrict__ bias) {
    const int g  = blockIdx.z;
    const int m0 = blockIdx.y * BM1;
    const int n0 = blockIdx.x * BN1;
    const int tid = threadIdx.x;

    __shared__ float As[BK1][BM1];
    __shared__ float Bs[BK1][BN1];
    __shared__ int   rowbase[BM1];

    if (tid < BM1) {
        int m  = m0 + tid;
        int bb = m >> 6;
        int s  = m & 63;
        rowbase[tid] = bb * NTOK + idx[g * SEQ + s];
    }
    __syncthreads();

    const int a_row = tid >> 1;
    const int a_col = (tid & 1) * 4;
    const int b_row = tid >> 5;
    const int b_col = (tid & 31) * 4;

    const float* Wg = W + (long)g * FDIM * DDIM;
    const long a_base = (long)rowbase[a_row] * FDIM;

    float acc[8][8];
#pragma unroll
    for (int i = 0; i < 8; i++)
#pragma unroll
        for (int j = 0; j < 8; j++) acc[i][j] = 0.f;

    const int ty = tid >> 4;
    const int tx = tid & 15;

    for (int k0 = 0; k0 < FDIM; k0 += BK1) {
        float4 av = *(const float4*)(x + a_base + k0 + a_col);
        As[a_col + 0][a_row] = av.x;
        As[a_col + 1][a_row] = av.y;
        As[a_col + 2][a_row] = av.z;
        As[a_col + 3][a_row] = av.w;
        *(float4*)&Bs[b_row][b_col] =
            *(const float4*)(Wg + (long)(k0 + b_row) * DDIM + n0 + b_col);
        __syncthreads();

#pragma unroll
        for (int kk = 0; kk < BK1; kk++) {
            float4 a0 = *(const float4*)&As[kk][ty * 4];
            float4 a1 = *(const float4*)&As[kk][64 + ty * 4];
            float4 c0 = *(const float4*)&Bs[kk][tx * 4];
            float4 c1 = *(const float4*)&Bs[kk][64 + tx * 4];
            float rm[8] = {a0.x, a0.y, a0.z, a0.w, a1.x, a1.y, a1.z, a1.w};
            float rn[8] = {c0.x, c0.y, c0.z, c0.w, c1.x, c1.y, c1.z, c1.w};
#pragma unroll
            for (int i = 0; i < 8; i++)
#pragma unroll
                for (int j = 0; j < 8; j++)
                    acc[i][j] += rm[i] * rn[j];
        }
        __syncthreads();
    }

#pragma unroll
    for (int i = 0; i < 8; i++) {
        int mi = (i < 4) ? (ty * 4 + i) : (64 + ty * 4 + (i - 4));
        int m  = m0 + mi;
        int bb = m >> 6;
        int s  = m & 63;
        unsigned* outrow = (unsigned*)(g_mid + ((long)(bb * NTOK + g * SEQ + s)) * DDIM + n0);
#pragma unroll
        for (int j = 0; j < 8; j++) {
            int nj = (j < 4) ? (tx * 4 + j) : (64 + tx * 4 + (j - 4));
            outrow[nj] = f2tf(acc[i][j] + bias[g * DDIM + n0 + nj]);
        }
    }
}

// ---------------------------------------------------------------------------
// Kernel 2: conv1d (window 32) as implicit GEMM, tf32 mma.sync
//   y[b, t, o] = leaky( sum_{k<8192} mid[b, t + k/256, k%256] * cw[k, o] + cb[o] )
//   Per batch: M = 993(pad 1024-ish), K = 8192, N = 512
// CTA tile 128x128x16, 8 warps (4m x 2n), warp tile 32x64, m16n8k8 tf32.
// ---------------------------------------------------------------------------
#define BK 16
#define AST 20    // A smem row stride (words): bank=(20g+t)&31 conflict-free
#define BST 136   // B smem row stride (words): bank=(8t+g)&31 conflict-free

__device__ __forceinline__ void cp16(unsigned smem, const float* g, int sz) {
    asm volatile("cp.async.ca.shared.global [%0], [%1], 16, %2;\n"
                 :: "r"(smem), "l"(g), "r"(sz));
}

__device__ __forceinline__ void mma_tf32(float* c, const unsigned* a, const unsigned* b) {
    asm volatile(
        "mma.sync.aligned.m16n8k8.row.col.f32.tf32.tf32.f32 "
        "{%0,%1,%2,%3}, {%4,%5,%6,%7}, {%8,%9}, {%0,%1,%2,%3};\n"
        : "+f"(c[0]), "+f"(c[1]), "+f"(c[2]), "+f"(c[3])
        : "r"(a[0]), "r"(a[1]), "r"(a[2]), "r"(a[3]), "r"(b[0]), "r"(b[1]));
}

__global__ __launch_bounds__(256, 2)
void conv_mma_kernel(const float* __restrict__ cb, float* __restrict__ y) {
    const int b  = blockIdx.z;
    const int t0 = blockIdx.y * 128;
    const int n0 = blockIdx.x * 128;
    const int tid  = threadIdx.x;
    const int lane = tid & 31;
    const int warp = tid >> 5;
    const int wm = warp >> 1;       // 0..3  -> m offset wm*32
    const int wn = warp & 1;        // 0..1  -> n offset wn*64
    const int g  = lane >> 2;       // groupID
    const int tl = lane & 3;        // threadID_in_group

    __shared__ float As[2][128][AST];
    __shared__ float Bs[2][BK][BST];

    const float* midb = g_mid + (long)b * NTOK * DDIM;

    // loader indices
    const int am0 = tid >> 2;            // A: row m (iter adds 64)
    const int ak0 = (tid & 3) * 4;       // A: k within stage
    const int bn0 = (tid & 31) * 4;      // B: n quad
    const int bk0 = tid >> 5;            // B: k row (iter adds 8)

    unsigned as_base = (unsigned)__cvta_generic_to_shared(&As[0][0][0]);
    unsigned bs_base = (unsigned)__cvta_generic_to_shared(&Bs[0][0][0]);
    const unsigned as_stage = 128 * AST * 4;
    const unsigned bs_stage = BK * BST * 4;

    float acc[2][8][4];
#pragma unroll
    for (int mt = 0; mt < 2; mt++)
#pragma unroll
        for (int nt = 0; nt < 8; nt++)
#pragma unroll
            for (int i = 0; i < 4; i++) acc[mt][nt][i] = 0.f;

    const int NSTAGE = (WIN * DDIM) / BK;   // 512

    // ---- issue stage 0
    {
        const int ks = 0;
        const int w = ks >> 8, d = ks & 255;
#pragma unroll
        for (int it = 0; it < 2; it++) {
            int m = am0 + it * 64;
            int t = t0 + m + w;
            cp16(as_base + (m * AST + ak0) * 4,
                 midb + (long)t * DDIM + d + ak0, (t < NTOK) ? 16 : 0);
        }
#pragma unroll
        for (int it = 0; it < 2; it++) {
            int k = bk0 + it * 8;
            cp16(bs_base + (k * BST + bn0) * 4,
                 g_cw + (long)(ks + k) * OCH + n0 + bn0, 16);
        }
        asm volatile("cp.async.commit_group;\n");
    }

#pragma unroll 1
    for (int s = 0; s < NSTAGE; s++) {
        asm volatile("cp.async.wait_group 0;\n");
        __syncthreads();

        // issue stage s+1 into the other buffer (overlaps with compute below)
        if (s + 1 < NSTAGE) {
            const int ks = (s + 1) * BK;
            const int w = ks >> 8, d = ks & 255;
            const unsigned ab = as_base + ((s + 1) & 1) * as_stage;
            const unsigned bb2 = bs_base + ((s + 1) & 1) * bs_stage;
#pragma unroll
            for (int it = 0; it < 2; it++) {
                int m = am0 + it * 64;
                int t = t0 + m + w;
                cp16(ab + (m * AST + ak0) * 4,
                     midb + (long)t * DDIM + d + ak0, (t < NTOK) ? 16 : 0);
            }
#pragma unroll
            for (int it = 0; it < 2; it++) {
                int k = bk0 + it * 8;
                cp16(bb2 + (k * BST + bn0) * 4,
                     g_cw + (long)(ks + k) * OCH + n0 + bn0, 16);
            }
            asm volatile("cp.async.commit_group;\n");
        }

        // compute current stage
        const int cur = s & 1;
#pragma unroll
        for (int kk = 0; kk < BK; kk += 8) {
            unsigned af[2][4];
#pragma unroll
            for (int mt = 0; mt < 2; mt++) {
                int rm = wm * 32 + mt * 16;
                af[mt][0] = __float_as_uint(As[cur][rm + g     ][kk + tl    ]);
                af[mt][1] = __float_as_uint(As[cur][rm + g + 8 ][kk + tl    ]);
                af[mt][2] = __float_as_uint(As[cur][rm + g     ][kk + tl + 4]);
                af[mt][3] = __float_as_uint(As[cur][rm + g + 8 ][kk + tl + 4]);
            }
            unsigned bf[8][2];
#pragma unroll
            for (int nt = 0; nt < 8; nt++) {
                int cn = wn * 64 + nt * 8;
                bf[nt][0] = __float_as_uint(Bs[cur][kk + tl    ][cn + g]);
                bf[nt][1] = __float_as_uint(Bs[cur][kk + tl + 4][cn + g]);
            }
#pragma unroll
            for (int mt = 0; mt < 2; mt++)
#pragma unroll
                for (int nt = 0; nt < 8; nt++)
                    mma_tf32(acc[mt][nt], af[mt], bf[nt]);
        }
        __syncthreads();
    }

    // ---- epilogue: bias + leaky relu
#pragma unroll
    for (int mt = 0; mt < 2; mt++) {
        int r0 = t0 + wm * 32 + mt * 16 + g;
        int r1 = r0 + 8;
#pragma unroll
        for (int nt = 0; nt < 8; nt++) {
            int c = n0 + wn * 64 + nt * 8 + 2 * tl;
            float2 bv = *(const float2*)(cb + c);
            if (r0 < TOUT) {
                float v0 = acc[mt][nt][0] + bv.x;
                float v1 = acc[mt][nt][1] + bv.y;
                v0 = (v0 >= 0.f) ? v0 : NEG_SLOPE * v0;
                v1 = (v1 >= 0.f) ? v1 : NEG_SLOPE * v1;
                *(float2*)(y + ((long)b * TOUT + r0) * OCH + c) = make_float2(v0, v1);
            }
            if (r1 < TOUT) {
                float v2 = acc[mt][nt][2] + bv.x;
                float v3 = acc[mt][nt][3] + bv.y;
                v2 = (v2 >= 0.f) ? v2 : NEG_SLOPE * v2;
                v3 = (v3 >= 0.f) ? v3 : NEG_SLOPE * v3;
                *(float2*)(y + ((long)b * TOUT + r1) * OCH + c) = make_float2(v2, v3);
            }
        }
    }
}

// ---------------------------------------------------------------------------
extern "C" void kernel_launch(void* const* d_in, const int* in_sizes, int n_in,
                              void* d_out, int out_size) {
    const float* x    = (const float*)d_in[0];
    const int*   idx  = (const int*)  d_in[1];
    const float* W    = (const float*)d_in[2];
    const float* bias = (const float*)d_in[3];
    const float* cw   = (const float*)d_in[4];
    const float* cb   = (const float*)d_in[5];
    float* y = (float*)d_out;

    cvt_cw_kernel<<<(WIN * DDIM * OCH) / (256 * 4), 256>>>(cw);

    dim3 grid1(DDIM / BN1, (BATCH * SEQ) / BM1, GRP);   // (2, 16, 16)
    gemm1_kernel<<<grid1, 256>>>(x, idx, W, bias);

    dim3 grid2(OCH / 128, (TOUT + 127) / 128, BATCH);    // (4, 8, 32)
    conv_mma_kernel<<<grid2, 256>>>(cb, y);
}

// round 4
// speedup vs baseline: 4.1942x; 1.3620x over previous
#include <cuda_runtime.h>
#include <cstdint>

// Problem constants
#define BATCH 32
#define NTOK  1024
#define FDIM  512
#define GRP   16
#define SEQ   64
#define DDIM  256
#define WIN   32
#define OCH   512
#define TOUT  993          // NTOK - WIN + 1
#define KTOT  (WIN * DDIM) // 8192
#define NEG_SLOPE 0.2f

// Scratch (device globals; no allocs allowed)
__device__ float g_mid[BATCH * NTOK * DDIM];          // 32 MB, tf32-rounded
__device__ float g_cwT[OCH * KTOT];                   // 16 MB, conv_w transposed [O][K], tf32
__device__ float g_wr [GRP * FDIM * DDIM];            // 8 MB, W tf32-rounded

__device__ __forceinline__ unsigned f2tf(float v) {
    unsigned r;
    asm("cvt.rna.tf32.f32 %0, %1;" : "=r"(r) : "f"(v));
    return r;
}

__device__ __forceinline__ void cp16(unsigned smem, const float* g, int sz) {
    asm volatile("cp.async.ca.shared.global [%0], [%1], 16, %2;\n"
                 :: "r"(smem), "l"(g), "r"(sz));
}

__device__ __forceinline__ void ldsm4(unsigned* r, unsigned addr) {
    asm volatile("ldmatrix.sync.aligned.m8n8.x4.shared.b16 {%0,%1,%2,%3}, [%4];"
                 : "=r"(r[0]), "=r"(r[1]), "=r"(r[2]), "=r"(r[3]) : "r"(addr));
}

__device__ __forceinline__ void mma_tf32(float* c, const unsigned* a, const unsigned* b) {
    asm volatile(
        "mma.sync.aligned.m16n8k8.row.col.f32.tf32.tf32.f32 "
        "{%0,%1,%2,%3}, {%4,%5,%6,%7}, {%8,%9}, {%0,%1,%2,%3};\n"
        : "+f"(c[0]), "+f"(c[1]), "+f"(c[2]), "+f"(c[3])
        : "r"(a[0]), "r"(a[1]), "r"(a[2]), "r"(a[3]), "r"(b[0]), "r"(b[1]));
}

// ===========================================================================
// Pre-pass kernels
// ===========================================================================
__global__ __launch_bounds__(256)
void cvt_w_kernel(const float* __restrict__ W) {
    int i = (blockIdx.x * 256 + threadIdx.x) * 4;
    float4 v = *(const float4*)(W + i);
    unsigned* o = (unsigned*)(g_wr + i);
    o[0] = f2tf(v.x); o[1] = f2tf(v.y); o[2] = f2tf(v.z); o[3] = f2tf(v.w);
}

// transpose conv_w [K=8192][O=512] -> g_cwT [O=512][K=8192], tf32-rounded
__global__ __launch_bounds__(256)
void trans_cw_kernel(const float* __restrict__ cw) {
    __shared__ float tile[32][33];
    const int o0 = blockIdx.x * 32;
    const int k0 = blockIdx.y * 32;
    const int tx = threadIdx.x & 31;
    const int ty = threadIdx.x >> 5;
#pragma unroll
    for (int j = 0; j < 4; j++) {
        int k = ty + j * 8;
        tile[k][tx] = __uint_as_float(f2tf(cw[(long)(k0 + k) * OCH + o0 + tx]));
    }
    __syncthreads();
#pragma unroll
    for (int j = 0; j < 4; j++) {
        int o = ty + j * 8;
        g_cwT[(long)(o0 + o) * KTOT + k0 + tx] = tile[tx][o];
    }
}

// ===========================================================================
// Kernel 1: gather + grouped GEMM via mma.sync tf32 (m16n8k8)
// CTA 128x128x16, 8 warps (4m x 2n), warp 32x64. M=2048, K=512, N=256.
// ===========================================================================
#define BK 16
#define AST 20
#define BST 136

__global__ __launch_bounds__(256, 2)
void gemm1_mma_kernel(const float* __restrict__ x, const int* __restrict__ idx,
                      const float* __restrict__ bias) {
    const int grp = blockIdx.z;
    const int m0  = blockIdx.y * 128;
    const int n0  = blockIdx.x * 128;
    const int tid  = threadIdx.x;
    const int lane = tid & 31;
    const int warp = tid >> 5;
    const int wm = warp >> 1;
    const int wn = warp & 1;
    const int gi = lane >> 2;
    const int tl = lane & 3;

    __shared__ float As[2][128][AST];
    __shared__ float Bs[2][BK][BST];
    __shared__ int   rowbase[128];

    if (tid < 128) {
        int m  = m0 + tid;
        int bb = m >> 6;
        int s  = m & 63;
        rowbase[tid] = bb * NTOK + idx[grp * SEQ + s];
    }
    __syncthreads();

    const int am0 = tid >> 2;
    const int ak0 = (tid & 3) * 4;
    const int bn0 = (tid & 31) * 4;
    const int bk0 = tid >> 5;

    const long arow0 = (long)rowbase[am0] * FDIM;
    const long arow1 = (long)rowbase[am0 + 64] * FDIM;
    const float* Bsrc = g_wr + (long)grp * FDIM * DDIM;

    unsigned as_base = (unsigned)__cvta_generic_to_shared(&As[0][0][0]);
    unsigned bs_base = (unsigned)__cvta_generic_to_shared(&Bs[0][0][0]);
    const unsigned as_stage = 128 * AST * 4;
    const unsigned bs_stage = BK * BST * 4;

    float acc[2][8][4];
#pragma unroll
    for (int mt = 0; mt < 2; mt++)
#pragma unroll
        for (int nt = 0; nt < 8; nt++)
#pragma unroll
            for (int i = 0; i < 4; i++) acc[mt][nt][i] = 0.f;

    const int NSTAGE = FDIM / BK;   // 32

    {
        cp16(as_base + (am0 * AST + ak0) * 4, x + arow0 + ak0, 16);
        cp16(as_base + ((am0 + 64) * AST + ak0) * 4, x + arow1 + ak0, 16);
#pragma unroll
        for (int it = 0; it < 2; it++) {
            int k = bk0 + it * 8;
            cp16(bs_base + (k * BST + bn0) * 4, Bsrc + (long)k * DDIM + n0 + bn0, 16);
        }
        asm volatile("cp.async.commit_group;\n");
    }

#pragma unroll 1
    for (int s = 0; s < NSTAGE; s++) {
        asm volatile("cp.async.wait_group 0;\n");
        __syncthreads();

        if (s + 1 < NSTAGE) {
            const int ks = (s + 1) * BK;
            const unsigned ab  = as_base + ((s + 1) & 1) * as_stage;
            const unsigned bb2 = bs_base + ((s + 1) & 1) * bs_stage;
            cp16(ab + (am0 * AST + ak0) * 4, x + arow0 + ks + ak0, 16);
            cp16(ab + ((am0 + 64) * AST + ak0) * 4, x + arow1 + ks + ak0, 16);
#pragma unroll
            for (int it = 0; it < 2; it++) {
                int k = bk0 + it * 8;
                cp16(bb2 + (k * BST + bn0) * 4, Bsrc + (long)(ks + k) * DDIM + n0 + bn0, 16);
            }
            asm volatile("cp.async.commit_group;\n");
        }

        const int cur = s & 1;
#pragma unroll
        for (int kk = 0; kk < BK; kk += 8) {
            unsigned af[2][4];
#pragma unroll
            for (int mt = 0; mt < 2; mt++) {
                int rm = wm * 32 + mt * 16;
                af[mt][0] = f2tf(As[cur][rm + gi     ][kk + tl    ]);
                af[mt][1] = f2tf(As[cur][rm + gi + 8 ][kk + tl    ]);
                af[mt][2] = f2tf(As[cur][rm + gi     ][kk + tl + 4]);
                af[mt][3] = f2tf(As[cur][rm + gi + 8 ][kk + tl + 4]);
            }
            unsigned bf[8][2];
#pragma unroll
            for (int nt = 0; nt < 8; nt++) {
                int cn = wn * 64 + nt * 8;
                bf[nt][0] = __float_as_uint(Bs[cur][kk + tl    ][cn + gi]);
                bf[nt][1] = __float_as_uint(Bs[cur][kk + tl + 4][cn + gi]);
            }
#pragma unroll
            for (int mt = 0; mt < 2; mt++)
#pragma unroll
                for (int nt = 0; nt < 8; nt++)
                    mma_tf32(acc[mt][nt], af[mt], bf[nt]);
        }
        __syncthreads();
    }

#pragma unroll
    for (int mt = 0; mt < 2; mt++) {
        int r0 = m0 + wm * 32 + mt * 16 + gi;
        int r1 = r0 + 8;
#pragma unroll
        for (int nt = 0; nt < 8; nt++) {
            int c = n0 + wn * 64 + nt * 8 + 2 * tl;
            float2 bv = *(const float2*)(bias + grp * DDIM + c);
            {
                int bb = r0 >> 6, s = r0 & 63;
                unsigned* dst = (unsigned*)(g_mid + ((long)(bb * NTOK + grp * SEQ + s)) * DDIM + c);
                dst[0] = f2tf(acc[mt][nt][0] + bv.x);
                dst[1] = f2tf(acc[mt][nt][1] + bv.y);
            }
            {
                int bb = r1 >> 6, s = r1 & 63;
                unsigned* dst = (unsigned*)(g_mid + ((long)(bb * NTOK + grp * SEQ + s)) * DDIM + c);
                dst[0] = f2tf(acc[mt][nt][2] + bv.x);
                dst[1] = f2tf(acc[mt][nt][3] + bv.y);
            }
        }
    }
}

// ===========================================================================
// Kernel 2: conv1d as implicit GEMM, mma.sync tf32 + ldmatrix fragments
//   CTA 128x128, 4 warps (2m x 2n), warp 64x64, BK=32, 3-stage cp.async.
//   A tile [128 m][32 k], B tile [128 n][32 k] (B from K-major g_cwT).
//   Rows are 128B; 16B chunks XOR-swizzled: chunk' = chunk ^ (row & 7).
// ===========================================================================
#define BKC 32
#define TILE_B 16384                 // 128 * 32 * 4
#define SM_A 0
#define SM_B (3 * TILE_B)
#define SM_TOTAL_CONV (6 * TILE_B)   // 96 KB

__global__ __launch_bounds__(128, 2)
void conv_mma_kernel(const float* __restrict__ cb, float* __restrict__ y) {
    extern __shared__ __align__(128) char smem[];
    unsigned smem_base;
    asm("{ .reg .u64 t; cvta.to.shared.u64 t, %1; cvt.u32.u64 %0, t; }"
        : "=r"(smem_base) : "l"(smem));

    const int b  = blockIdx.z;
    const int t0 = blockIdx.y * 128;
    const int n0 = blockIdx.x * 128;
    const int tid  = threadIdx.x;
    const int lane = tid & 31;
    const int warp = tid >> 5;
    const int wm = warp >> 1;        // 0..1 -> m offset wm*64
    const int wn = warp & 1;         // 0..1 -> n offset wn*64
    const int gi = lane >> 2;
    const int tl = lane & 3;
    const int grp8 = lane >> 3;      // 0..3
    const int r8   = lane & 7;

    const float* midb = g_mid + (long)b * NTOK * DDIM;

    float acc[4][8][4];
#pragma unroll
    for (int mt = 0; mt < 4; mt++)
#pragma unroll
        for (int nt = 0; nt < 8; nt++)
#pragma unroll
            for (int i = 0; i < 4; i++) acc[mt][nt][i] = 0.f;

    const int NS = KTOT / BKC;   // 256

    auto load_stage = [&](int it) {
        const int ks = it * BKC;
        const int w  = ks >> 8;
        const int d0 = ks & 255;
        const int buf = it % 3;
        const unsigned abase = smem_base + SM_A + buf * TILE_B;
        const unsigned bbase = smem_base + SM_B + buf * TILE_B;
#pragma unroll
        for (int i = 0; i < 8; i++) {
            int c   = tid + i * 128;        // 0..1023
            int row = c >> 3;
            int ch  = c & 7;
            int t   = t0 + row + w;
            cp16(abase + row * 128 + ((ch ^ (row & 7)) * 16),
                 midb + (long)t * DDIM + d0 + ch * 4, (t < NTOK) ? 16 : 0);
        }
#pragma unroll
        for (int i = 0; i < 8; i++) {
            int c   = tid + i * 128;
            int row = c >> 3;
            int ch  = c & 7;
            cp16(bbase + row * 128 + ((ch ^ (row & 7)) * 16),
                 g_cwT + (long)(n0 + row) * KTOT + ks + ch * 4, 16);
        }
        asm volatile("cp.async.commit_group;\n");
    };

    load_stage(0);
    load_stage(1);

#pragma unroll 1
    for (int s = 0; s < NS; s++) {
        if (s + 1 < NS) asm volatile("cp.async.wait_group 1;\n");
        else            asm volatile("cp.async.wait_group 0;\n");
        __syncthreads();

        if (s + 2 < NS) load_stage(s + 2);

        const int buf = s % 3;
        const unsigned abase = smem_base + SM_A + buf * TILE_B;
        const unsigned bbase = smem_base + SM_B + buf * TILE_B;

#pragma unroll
        for (int kk = 0; kk < BKC; kk += 8) {
            const int kc = kk >> 2;
            unsigned af[4][4];
#pragma unroll
            for (int mt = 0; mt < 4; mt++) {
                int row = wm * 64 + mt * 16 + (grp8 & 1) * 8 + r8;
                int ch  = kc + (grp8 >> 1);
                ldsm4(af[mt], abase + row * 128 + ((ch ^ (row & 7)) * 16));
            }
            unsigned bf[4][4];   // bf[q]: {b0,b1} of n-block 2q, {b0,b1} of 2q+1
#pragma unroll
            for (int q = 0; q < 4; q++) {
                int row = wn * 64 + q * 16 + (grp8 >> 1) * 8 + r8;
                int ch  = kc + (grp8 & 1);
                ldsm4(bf[q], bbase + row * 128 + ((ch ^ (row & 7)) * 16));
            }
#pragma unroll
            for (int mt = 0; mt < 4; mt++)
#pragma unroll
                for (int nt = 0; nt < 8; nt++)
                    mma_tf32(acc[mt][nt], af[mt], &bf[nt >> 1][(nt & 1) * 2]);
        }
        __syncthreads();
    }

    // epilogue: bias + leaky relu
#pragma unroll
    for (int mt = 0; mt < 4; mt++) {
        int r0 = t0 + wm * 64 + mt * 16 + gi;
        int r1 = r0 + 8;
#pragma unroll
        for (int nt = 0; nt < 8; nt++) {
            int c = n0 + wn * 64 + nt * 8 + 2 * tl;
            float2 bv = *(const float2*)(cb + c);
            if (r0 < TOUT) {
                float v0 = acc[mt][nt][0] + bv.x;
                float v1 = acc[mt][nt][1] + bv.y;
                v0 = (v0 >= 0.f) ? v0 : NEG_SLOPE * v0;
                v1 = (v1 >= 0.f) ? v1 : NEG_SLOPE * v1;
                *(float2*)(y + ((long)b * TOUT + r0) * OCH + c) = make_float2(v0, v1);
            }
            if (r1 < TOUT) {
                float v2 = acc[mt][nt][2] + bv.x;
                float v3 = acc[mt][nt][3] + bv.y;
                v2 = (v2 >= 0.f) ? v2 : NEG_SLOPE * v2;
                v3 = (v3 >= 0.f) ? v3 : NEG_SLOPE * v3;
                *(float2*)(y + ((long)b * TOUT + r1) * OCH + c) = make_float2(v2, v3);
            }
        }
    }
}

// ===========================================================================
extern "C" void kernel_launch(void* const* d_in, const int* in_sizes, int n_in,
                              void* d_out, int out_size) {
    const float* x    = (const float*)d_in[0];
    const int*   idx  = (const int*)  d_in[1];
    const float* W    = (const float*)d_in[2];
    const float* bias = (const float*)d_in[3];
    const float* cw   = (const float*)d_in[4];
    const float* cb   = (const float*)d_in[5];
    float* y = (float*)d_out;

    cudaFuncSetAttribute(conv_mma_kernel,
                         cudaFuncAttributeMaxDynamicSharedMemorySize, SM_TOTAL_CONV);

    cvt_w_kernel<<<(GRP * FDIM * DDIM) / (256 * 4), 256>>>(W);
    trans_cw_kernel<<<dim3(OCH / 32, KTOT / 32), 256>>>(cw);

    dim3 grid1(DDIM / 128, (BATCH * SEQ) / 128, GRP);   // (2, 16, 16)
    gemm1_mma_kernel<<<grid1, 256>>>(x, idx, bias);

    dim3 grid2(OCH / 128, NTOK / 128, BATCH);           // (4, 8, 32)
    conv_mma_kernel<<<grid2, 128, SM_TOTAL_CONV>>>(cb, y);
}